// round 1
// baseline (speedup 1.0000x reference)
#include <cuda_runtime.h>
#include <cstdint>

typedef unsigned long long ull;

// ---------------------------------------------------------------------------
// Packed fp32x2 helpers (sm_100+): FFMA2 restores full 128 FMA/cyc/SM rate.
// ---------------------------------------------------------------------------
__device__ __forceinline__ ull pack_dup(float a) {
    ull r;
    asm("mov.b64 %0, {%1, %1};" : "=l"(r) : "f"(a));
    return r;
}
__device__ __forceinline__ ull ffma2(ull a, ull b, ull c) {
    ull d;
    asm("fma.rn.f32x2 %0, %1, %2, %3;" : "=l"(d) : "l"(a), "l"(b), "l"(c));
    return d;
}
__device__ __forceinline__ void unpack2(ull v, float& lo, float& hi) {
    asm("mov.b64 {%0, %1}, %2;" : "=f"(lo), "=f"(hi) : "l"(v));
}

// ---------------------------------------------------------------------------
// Weight scratch: W[32][144][3][3][3] transposed+paired into
//   g_Wt[(ci*27 + tap)*16 + p] = { W[2p][ci][tap], W[2p+1][ci][tap] }
// so the conv kernel streams conflict-free, coalesced float4s of co-pairs.
// 144*27*16 float2 = 995 KB (device global scratch; no allocations).
// ---------------------------------------------------------------------------
__device__ __align__(16) float2 g_Wt[144 * 27 * 16];

__global__ void wt_transpose_kernel(const float* __restrict__ W) {
    int i = blockIdx.x * 256 + threadIdx.x;
    if (i >= 144 * 27 * 16) return;
    int p   = i & 15;
    int tap = (i >> 4) % 27;
    int ci  = i / (16 * 27);
    int co  = 2 * p;
    float2 v;
    v.x = W[(size_t)co * 3888 + ci * 27 + tap];
    v.y = W[(size_t)(co + 1) * 3888 + ci * 27 + tap];
    g_Wt[i] = v;
}

// ---------------------------------------------------------------------------
// Direct conv, FFMA2 packed over output-channel pairs.
//   Block = 128 threads; 125 active, each owns (x,y) and 2 consecutive z.
//   Block tile = 5x5x10 outputs, all 32 c_out. Grid = (6*6*3 tiles, 8 batch).
//   30 = 6*5 = 3*10 -> zero spatial boundary waste, no predicates in hot loop.
//   smem: input chunk [8ci][7][7][12] (18.8 KB) + W chunk [8ci][27][16 pairs]
//   (27.6 KB) = 46.4 KB static.
// ---------------------------------------------------------------------------
__global__ __launch_bounds__(128, 3)
void conv_kernel(const float* __restrict__ x, float* __restrict__ out) {
    __shared__ float s_in[8 * 588];                       // [ci][7][7][12]
    __shared__ __align__(16) float2 s_w[8 * 432];         // [ci][27][16]

    const int tid = threadIdx.x;
    const int t   = blockIdx.x;          // 0..107
    const int b   = blockIdx.y;          // 0..7
    const int bz  = t % 3;
    const int by  = (t / 3) % 6;
    const int bx  = t / 18;

    const int tc = (tid < 125) ? tid : 124;   // inactive lanes compute garbage safely
    const int tz = tc % 5;
    const int ty = (tc / 5) % 5;
    const int tx = tc / 25;

    const int gx0 = bx * 5, gy0 = by * 5, gz0 = bz * 10;

    ull acc0[16], acc1[16];   // acc0: z=oz, acc1: z=oz+1; each ull = {co=2p, co=2p+1}
#pragma unroll
    for (int p = 0; p < 16; p++) { acc0[p] = 0ull; acc1[p] = 0ull; }

    const int in_base = tx * 84 + ty * 12 + 2 * tz;
    const float* xb = x + (size_t)b * 144 * 32768;

    for (int ci0 = 0; ci0 < 144; ci0 += 8) {
        __syncthreads();   // previous chunk's smem reads complete before overwrite

        // ---- stage input tile chunk: 8 ci * 7*7*12 floats ----
        for (int idx = tid; idx < 8 * 588; idx += 128) {
            int ci = idx / 588;
            int r  = idx - ci * 588;
            int xx = r / 84;
            int r2 = r - xx * 84;
            int yy = r2 / 12;
            int zz = r2 - yy * 12;
            s_in[idx] = xb[(size_t)(ci0 + ci) * 32768
                           + (size_t)(gx0 + xx) * 1024
                           + (gy0 + yy) * 32 + (gz0 + zz)];
        }
        // ---- stage weight chunk (coalesced float4 of co-pairs) ----
        {
            const float4* src = (const float4*)(g_Wt + (size_t)ci0 * 432);
            float4* dst = (float4*)s_w;
            for (int idx = tid; idx < (8 * 432) / 2; idx += 128)
                dst[idx] = src[idx];
        }
        __syncthreads();

#pragma unroll 1
        for (int ci = 0; ci < 8; ci++) {
            const float*  pin0 = s_in + ci * 588 + in_base;
            const float2* pw0  = s_w + ci * 432;
#pragma unroll
            for (int kx = 0; kx < 3; kx++) {
#pragma unroll
                for (int ky = 0; ky < 3; ky++) {
                    const float* p = pin0 + kx * 84 + ky * 12;
                    // 4 consecutive z values serve all 3 kz taps for both z outputs
                    ull v[4];
                    v[0] = pack_dup(p[0]);
                    v[1] = pack_dup(p[1]);
                    v[2] = pack_dup(p[2]);
                    v[3] = pack_dup(p[3]);
                    const float2* pw = pw0 + (kx * 9 + ky * 3) * 16;
#pragma unroll
                    for (int kz = 0; kz < 3; kz++) {
                        const ulonglong2* w = (const ulonglong2*)(pw + kz * 16);
#pragma unroll
                        for (int j = 0; j < 8; j++) {
                            ulonglong2 ww = w[j];          // 4 c_out weights (2 pairs), broadcast
                            acc0[2 * j]     = ffma2(v[kz],     ww.x, acc0[2 * j]);
                            acc0[2 * j + 1] = ffma2(v[kz],     ww.y, acc0[2 * j + 1]);
                            acc1[2 * j]     = ffma2(v[kz + 1], ww.x, acc1[2 * j]);
                            acc1[2 * j + 1] = ffma2(v[kz + 1], ww.y, acc1[2 * j + 1]);
                        }
                    }
                }
            }
        }
    }

    // ---- epilogue: 32 c_out x 2 z per thread, vectorized along z ----
    if (tid < 125) {
        const int ox = gx0 + tx, oy = gy0 + ty, oz = gz0 + 2 * tz;
        float* ob = out + (size_t)b * 32 * 27000 + ox * 900 + oy * 30 + oz;
#pragma unroll
        for (int p = 0; p < 16; p++) {
            float a0lo, a0hi, a1lo, a1hi;
            unpack2(acc0[p], a0lo, a0hi);
            unpack2(acc1[p], a1lo, a1hi);
            float2 c0 = make_float2(a0lo, a1lo);   // co=2p,   z=oz..oz+1 (8B aligned)
            float2 c1 = make_float2(a0hi, a1hi);   // co=2p+1
            *(float2*)(ob + (size_t)(2 * p) * 27000)     = c0;
            *(float2*)(ob + (size_t)(2 * p + 1) * 27000) = c1;
        }
    }
}

// ---------------------------------------------------------------------------
extern "C" void kernel_launch(void* const* d_in, const int* in_sizes, int n_in,
                              void* d_out, int out_size) {
    const float* x = (const float*)d_in[0];
    const float* W = (const float*)d_in[1];
    // defensive: identify by element count (x = 37,748,736; W = 124,416)
    if (n_in >= 2 && in_sizes[0] == 124416) {
        const float* tmp = x; x = W; W = tmp;
    }
    float* out = (float*)d_out;

    wt_transpose_kernel<<<(144 * 27 * 16 + 255) / 256, 256>>>(W);

    dim3 grid(108, 8);   // 6*6*3 spatial tiles x 8 batches
    conv_kernel<<<grid, 128>>>(x, out);
}

// round 4
// speedup vs baseline: 1.0389x; 1.0389x over previous
#include <cuda_runtime.h>
#include <cstdint>

typedef unsigned long long ull;

// ---------------------------------------------------------------------------
// Packed fp32x2 helpers (sm_100+): FFMA2 gives full 128 FMA/cyc/SM rate.
// ---------------------------------------------------------------------------
__device__ __forceinline__ ull pack_dup(float a) {
    ull r;
    asm("mov.b64 %0, {%1, %1};" : "=l"(r) : "f"(a));
    return r;
}
__device__ __forceinline__ ull ffma2(ull a, ull b, ull c) {
    ull d;
    asm("fma.rn.f32x2 %0, %1, %2, %3;" : "=l"(d) : "l"(a), "l"(b), "l"(c));
    return d;
}
__device__ __forceinline__ void unpack2(ull v, float& lo, float& hi) {
    asm("mov.b64 {%0, %1}, %2;" : "=f"(lo), "=f"(hi) : "l"(v));
}
__device__ __forceinline__ uint32_t sptr(const void* p) {
    return (uint32_t)__cvta_generic_to_shared(p);
}
__device__ __forceinline__ void cp16(uint32_t s, const void* g) {
    asm volatile("cp.async.cg.shared.global [%0], [%1], 16;" :: "r"(s), "l"(g));
}
__device__ __forceinline__ void cp_commit() {
    asm volatile("cp.async.commit_group;");
}
__device__ __forceinline__ void cp_wait1() {
    asm volatile("cp.async.wait_group 1;" ::: "memory");
}
__device__ __forceinline__ void cp_wait0() {
    asm volatile("cp.async.wait_group 0;" ::: "memory");
}

// ---------------------------------------------------------------------------
// Weight scratch: W[32][144][3][3][3] transposed+paired into
//   g_Wt[(ci*27 + tap)*16 + p] = { W[2p][ci][tap], W[2p+1][ci][tap] }
// ---------------------------------------------------------------------------
__device__ __align__(16) float2 g_Wt[144 * 27 * 16];

__global__ void wt_transpose_kernel(const float* __restrict__ W) {
    int i = blockIdx.x * 256 + threadIdx.x;
    if (i >= 144 * 27 * 16) return;
    int p   = i & 15;
    int tap = (i >> 4) % 27;
    int ci  = i / (16 * 27);
    int co  = 2 * p;
    float2 v;
    v.x = W[(size_t)co * 3888 + ci * 27 + tap];
    v.y = W[(size_t)(co + 1) * 3888 + ci * 27 + tap];
    g_Wt[i] = v;
}

// ---------------------------------------------------------------------------
// Staging: one chunk = 2 input channels. Inlined (no lambda).
//   input: 2ci * 5x * 5y * 32z floats = 400 float4 via cp.async
//   weights: 2ci * 27tap * 16pairs float2 = 432 float4 via cp.async
// ---------------------------------------------------------------------------
__device__ __forceinline__ void stage_chunk(
    const float* __restrict__ xb, int ci0, int tid,
    float* __restrict__ sin_buf, float2* __restrict__ sw_buf)
{
    for (int idx = tid; idx < 400; idx += 192) {
        int ci = idx / 200;
        int r  = idx - ci * 200;
        int xx = r / 40;
        int r2 = r - xx * 40;
        int yy = r2 >> 3;
        int zi = r2 & 7;
        cp16(sptr(&sin_buf[ci * 800 + xx * 160 + yy * 32 + zi * 4]),
             xb + (size_t)(ci0 + ci) * 32768 + xx * 1024 + yy * 32 + zi * 4);
    }
    const float4* gw = (const float4*)g_Wt + (size_t)ci0 * 216;
    float4* sw = (float4*)sw_buf;
    for (int idx = tid; idx < 432; idx += 192)
        cp16(sptr(sw + idx), gw + idx);
}

// ---------------------------------------------------------------------------
// Direct conv, FFMA2, tiled to amortize weight LDS.
//   Block tile: 3x * 3y * 30z, all 32 c_out. Grid = 10*10 x 8 batch.
//   192 threads: tid = sp*4 + cg.  cg owns c_out [8cg, 8cg+8); sp spatial:
//   sp = x*15 + y*5 + zg (x,y in 0..2, zg in 0..4), thread z = zg*6 .. +5.
//   Per 16B weight load: 2 co-pairs x 6 z = 12 FFMA2.
//   Input LDS are 4-way lane-broadcast (same sp in adjacent lanes).
//   smem: double-buffered 2-ci chunks: 26.6 KB total, cp.async pipelined.
// ---------------------------------------------------------------------------
__global__ __launch_bounds__(192, 3)
void conv_kernel(const float* __restrict__ x, float* __restrict__ out) {
    __shared__ __align__(16) float  s_in[2][1600];   // [ci2][x5][y5][z32]
    __shared__ __align__(16) float2 s_w [2][864];    // [ci2][27 tap][16 pairs]

    const int tid = threadIdx.x;
    const int cg  = tid & 3;
    const int sp  = tid >> 2;                 // 0..47, active < 45
    const int spc = (sp < 45) ? sp : 44;
    const int txi = spc / 15;
    const int tyi = (spc / 5) % 3;
    const int tzg = spc % 5;

    const int bx = blockIdx.x % 10, by = blockIdx.x / 10;
    const int b  = blockIdx.y;
    const int gx0 = bx * 3, gy0 = by * 3;

    const float* xb = x + (size_t)b * 144 * 32768 + (size_t)gx0 * 1024 + gy0 * 32;

    ull acc[4][6];
#pragma unroll
    for (int p = 0; p < 4; p++)
#pragma unroll
        for (int z = 0; z < 6; z++) acc[p][z] = 0ull;

    stage_chunk(xb, 0, tid, s_in[0], s_w[0]);
    cp_commit();

    const int in_base = txi * 160 + tyi * 32 + tzg * 6;
    const int w_base  = cg * 4;

    for (int c = 0; c < 72; c++) {
        const int buf = c & 1;
        __syncthreads();                    // readers of buf^1 (chunk c-1) done
        if (c + 1 < 72) {
            stage_chunk(xb, (c + 1) * 2, tid, s_in[buf ^ 1], s_w[buf ^ 1]);
            cp_commit();
            cp_wait1();                     // chunk c landed; c+1 in flight
        } else {
            cp_wait0();                     // final chunk landed
        }
        __syncthreads();

#pragma unroll 1
        for (int ci = 0; ci < 2; ci++) {
            const float*  pin = &s_in[buf][ci * 800] + in_base;
            const float2* pw  = &s_w[buf][ci * 432] + w_base;
#pragma unroll
            for (int kx = 0; kx < 3; kx++) {
#pragma unroll
                for (int ky = 0; ky < 3; ky++) {
                    const float* p = pin + kx * 160 + ky * 32;
                    ull v[8];
#pragma unroll
                    for (int j = 0; j < 8; j++) v[j] = pack_dup(p[j]);
#pragma unroll
                    for (int kz = 0; kz < 3; kz++) {
                        const ulonglong2* w =
                            (const ulonglong2*)(pw + (kx * 9 + ky * 3 + kz) * 16);
                        ulonglong2 w0 = w[0], w1 = w[1];   // this cg's 4 co-pairs
#pragma unroll
                        for (int z = 0; z < 6; z++) {
                            acc[0][z] = ffma2(v[z + kz], w0.x, acc[0][z]);
                            acc[1][z] = ffma2(v[z + kz], w0.y, acc[1][z]);
                            acc[2][z] = ffma2(v[z + kz], w1.x, acc[2][z]);
                            acc[3][z] = ffma2(v[z + kz], w1.y, acc[3][z]);
                        }
                    }
                }
            }
        }
    }

    // ---- epilogue: 8 c_out x 6 contiguous z per thread ----
    if (sp < 45) {
        float* ob = out + ((size_t)b * 32 + 8 * cg) * 27000
                        + (gx0 + txi) * 900 + (gy0 + tyi) * 30 + tzg * 6;
#pragma unroll
        for (int p = 0; p < 4; p++) {
            float lo, hi;
#pragma unroll
            for (int z = 0; z < 6; z++) {
                unpack2(acc[p][z], lo, hi);
                ob[(2 * p) * 27000 + z]     = lo;
                ob[(2 * p + 1) * 27000 + z] = hi;
            }
        }
    }
}

// ---------------------------------------------------------------------------
extern "C" void kernel_launch(void* const* d_in, const int* in_sizes, int n_in,
                              void* d_out, int out_size) {
    const float* x = (const float*)d_in[0];
    const float* W = (const float*)d_in[1];
    if (n_in >= 2 && in_sizes[0] == 124416) {   // defensive swap by element count
        const float* tmp = x; x = W; W = tmp;
    }
    float* out = (float*)d_out;

    wt_transpose_kernel<<<(144 * 27 * 16 + 255) / 256, 256>>>(W);

    dim3 grid(100, 8);   // 10x10 (x,y) tiles x 8 batches; full z per block
    conv_kernel<<<grid, 192>>>(x, out);
}

// round 5
// speedup vs baseline: 1.0392x; 1.0003x over previous
#include <cuda_runtime.h>
#include <cstdint>

typedef unsigned long long ull;

// ---------------------------------------------------------------------------
// Packed fp32x2 helpers (sm_100+): FFMA2 gives full 128 FMA/cyc/SM rate.
// ---------------------------------------------------------------------------
__device__ __forceinline__ ull pack_dup(float a) {
    ull r;
    asm("mov.b64 %0, {%1, %1};" : "=l"(r) : "f"(a));
    return r;
}
__device__ __forceinline__ ull ffma2(ull a, ull b, ull c) {
    ull d;
    asm("fma.rn.f32x2 %0, %1, %2, %3;" : "=l"(d) : "l"(a), "l"(b), "l"(c));
    return d;
}
__device__ __forceinline__ void unpack2(ull v, float& lo, float& hi) {
    asm("mov.b64 {%0, %1}, %2;" : "=f"(lo), "=f"(hi) : "l"(v));
}
__device__ __forceinline__ uint32_t sptr(const void* p) {
    return (uint32_t)__cvta_generic_to_shared(p);
}
__device__ __forceinline__ void cp16(uint32_t s, const void* g) {
    asm volatile("cp.async.cg.shared.global [%0], [%1], 16;" :: "r"(s), "l"(g));
}
__device__ __forceinline__ void cp_commit() {
    asm volatile("cp.async.commit_group;");
}
__device__ __forceinline__ void cp_wait1() {
    asm volatile("cp.async.wait_group 1;" ::: "memory");
}
__device__ __forceinline__ void cp_wait0() {
    asm volatile("cp.async.wait_group 0;" ::: "memory");
}

// ---------------------------------------------------------------------------
// Weight scratch: W[32][144][3][3][3] transposed+paired into
//   g_Wt[(ci*27 + tap)*16 + p] = { W[2p][ci][tap], W[2p+1][ci][tap] }
// ---------------------------------------------------------------------------
__device__ __align__(16) float2 g_Wt[144 * 27 * 16];

__global__ void wt_transpose_kernel(const float* __restrict__ W) {
    int i = blockIdx.x * 256 + threadIdx.x;
    if (i >= 144 * 27 * 16) return;
    int p   = i & 15;
    int tap = (i >> 4) % 27;
    int ci  = i / (16 * 27);
    int co  = 2 * p;
    float2 v;
    v.x = W[(size_t)co * 3888 + ci * 27 + tap];
    v.y = W[(size_t)(co + 1) * 3888 + ci * 27 + tap];
    g_Wt[i] = v;
}

// ---------------------------------------------------------------------------
// Staging: one chunk = 2 input channels. Inlined (no lambda).
//   input: 2ci * 5x * 5y * 32z floats = 400 float4 via cp.async
//   weights: 2ci * 27tap * 16pairs float2 = 432 float4 via cp.async
// ---------------------------------------------------------------------------
__device__ __forceinline__ void stage_chunk(
    const float* __restrict__ xb, int ci0, int tid,
    float* __restrict__ sin_buf, float2* __restrict__ sw_buf)
{
    for (int idx = tid; idx < 400; idx += 192) {
        int ci = idx / 200;
        int r  = idx - ci * 200;
        int xx = r / 40;
        int r2 = r - xx * 40;
        int yy = r2 >> 3;
        int zi = r2 & 7;
        cp16(sptr(&sin_buf[ci * 800 + xx * 160 + yy * 32 + zi * 4]),
             xb + (size_t)(ci0 + ci) * 32768 + xx * 1024 + yy * 32 + zi * 4);
    }
    const float4* gw = (const float4*)g_Wt + (size_t)ci0 * 216;
    float4* sw = (float4*)sw_buf;
    for (int idx = tid; idx < 432; idx += 192)
        cp16(sptr(sw + idx), gw + idx);
}

// ---------------------------------------------------------------------------
// Direct conv, FFMA2, tiled to amortize weight LDS.
//   Block tile: 3x * 3y * 30z, all 32 c_out. Grid = 10*10 x 8 batch.
//   192 threads: tid = sp*4 + cg.  cg owns c_out [8cg, 8cg+8); sp spatial:
//   sp = x*15 + y*5 + zg (x,y in 0..2, zg in 0..4), thread z = zg*6 .. +5.
//   Per 16B weight load: 2 co-pairs x 6 z = 12 FFMA2.
//   Input LDS are 4-way lane-broadcast (same sp in adjacent lanes).
//   smem: double-buffered 2-ci chunks: 26.6 KB total, cp.async pipelined.
// ---------------------------------------------------------------------------
__global__ __launch_bounds__(192, 3)
void conv_kernel(const float* __restrict__ x, float* __restrict__ out) {
    __shared__ __align__(16) float  s_in[2][1600];   // [ci2][x5][y5][z32]
    __shared__ __align__(16) float2 s_w [2][864];    // [ci2][27 tap][16 pairs]

    const int tid = threadIdx.x;
    const int cg  = tid & 3;
    const int sp  = tid >> 2;                 // 0..47, active < 45
    const int spc = (sp < 45) ? sp : 44;
    const int txi = spc / 15;
    const int tyi = (spc / 5) % 3;
    const int tzg = spc % 5;

    const int bx = blockIdx.x % 10, by = blockIdx.x / 10;
    const int b  = blockIdx.y;
    const int gx0 = bx * 3, gy0 = by * 3;

    const float* xb = x + (size_t)b * 144 * 32768 + (size_t)gx0 * 1024 + gy0 * 32;

    ull acc[4][6];
#pragma unroll
    for (int p = 0; p < 4; p++)
#pragma unroll
        for (int z = 0; z < 6; z++) acc[p][z] = 0ull;

    stage_chunk(xb, 0, tid, s_in[0], s_w[0]);
    cp_commit();

    const int in_base = txi * 160 + tyi * 32 + tzg * 6;
    const int w_base  = cg * 4;

    for (int c = 0; c < 72; c++) {
        const int buf = c & 1;
        __syncthreads();                    // readers of buf^1 (chunk c-1) done
        if (c + 1 < 72) {
            stage_chunk(xb, (c + 1) * 2, tid, s_in[buf ^ 1], s_w[buf ^ 1]);
            cp_commit();
            cp_wait1();                     // chunk c landed; c+1 in flight
        } else {
            cp_wait0();                     // final chunk landed
        }
        __syncthreads();

#pragma unroll 1
        for (int ci = 0; ci < 2; ci++) {
            const float*  pin = &s_in[buf][ci * 800] + in_base;
            const float2* pw  = &s_w[buf][ci * 432] + w_base;
#pragma unroll
            for (int kx = 0; kx < 3; kx++) {
#pragma unroll
                for (int ky = 0; ky < 3; ky++) {
                    const float* p = pin + kx * 160 + ky * 32;
                    ull v[8];
#pragma unroll
                    for (int j = 0; j < 8; j++) v[j] = pack_dup(p[j]);
#pragma unroll
                    for (int kz = 0; kz < 3; kz++) {
                        const ulonglong2* w =
                            (const ulonglong2*)(pw + (kx * 9 + ky * 3 + kz) * 16);
                        ulonglong2 w0 = w[0], w1 = w[1];   // this cg's 4 co-pairs
#pragma unroll
                        for (int z = 0; z < 6; z++) {
                            acc[0][z] = ffma2(v[z + kz], w0.x, acc[0][z]);
                            acc[1][z] = ffma2(v[z + kz], w0.y, acc[1][z]);
                            acc[2][z] = ffma2(v[z + kz], w1.x, acc[2][z]);
                            acc[3][z] = ffma2(v[z + kz], w1.y, acc[3][z]);
                        }
                    }
                }
            }
        }
    }

    // ---- epilogue: 8 c_out x 6 contiguous z per thread ----
    if (sp < 45) {
        float* ob = out + ((size_t)b * 32 + 8 * cg) * 27000
                        + (gx0 + txi) * 900 + (gy0 + tyi) * 30 + tzg * 6;
#pragma unroll
        for (int p = 0; p < 4; p++) {
            float lo, hi;
#pragma unroll
            for (int z = 0; z < 6; z++) {
                unpack2(acc[p][z], lo, hi);
                ob[(2 * p) * 27000 + z]     = lo;
                ob[(2 * p + 1) * 27000 + z] = hi;
            }
        }
    }
}

// ---------------------------------------------------------------------------
extern "C" void kernel_launch(void* const* d_in, const int* in_sizes, int n_in,
                              void* d_out, int out_size) {
    const float* x = (const float*)d_in[0];
    const float* W = (const float*)d_in[1];
    if (n_in >= 2 && in_sizes[0] == 124416) {   // defensive swap by element count
        const float* tmp = x; x = W; W = tmp;
    }
    float* out = (float*)d_out;

    wt_transpose_kernel<<<(144 * 27 * 16 + 255) / 256, 256>>>(W);

    dim3 grid(100, 8);   // 10x10 (x,y) tiles x 8 batches; full z per block
    conv_kernel<<<grid, 192>>>(x, out);
}

// round 11
// speedup vs baseline: 1.8448x; 1.7752x over previous
// R11: verbatim resubmit of the R9 fragment-order fix (two broker flakes in a row;
// R8 sibling of this binary executed fine on-GPU, so this cannot hang or fault).
#include <cuda_runtime.h>
#include <cuda_bf16.h>
#include <cstdint>

#define DINL __device__ __forceinline__

// ---------------- device scratch (no allocations allowed) -------------------
// x channel-last bf16 hi/lo: row = flat(b,x,y,z), 144 ci per row (288B).
// +1024 pad rows: kz/oy window shifts can read past a slab end; those products
// land only in discarded oz>=30 / oy>=30 outputs. .bss is zero-initialized.
__device__ __align__(16) __nv_bfloat16 g_xh[(262144 + 1024) * 144];
__device__ __align__(16) __nv_bfloat16 g_xl[(262144 + 1024) * 144];
// W rows: [(kx*3+kz)*9 + chunk*3 + ky][co32][ci64] = 2592 rows x 128B
__device__ __align__(16) __nv_bfloat16 g_bh[2592 * 64];
__device__ __align__(16) __nv_bfloat16 g_bl[2592 * 64];

// ---------------- PTX helpers ----------------------------------------------
DINL uint32_t smem_u32(const void* p) {
    uint32_t a;
    asm("{ .reg .u64 t; cvta.to.shared.u64 t, %1; cvt.u32.u64 %0, t; }" : "=r"(a) : "l"(p));
    return a;
}
DINL void cp16(uint32_t s, const void* g) {
    asm volatile("cp.async.cg.shared.global [%0], [%1], 16;" :: "r"(s), "l"(g));
}
DINL void cp_commit() { asm volatile("cp.async.commit_group;"); }
DINL void cp_wait1()  { asm volatile("cp.async.wait_group 1;" ::: "memory"); }
DINL void cp_wait0()  { asm volatile("cp.async.wait_group 0;" ::: "memory"); }

DINL void ldm4(uint32_t& r0, uint32_t& r1, uint32_t& r2, uint32_t& r3, uint32_t a) {
    asm volatile("ldmatrix.sync.aligned.m8n8.x4.shared.b16 {%0,%1,%2,%3}, [%4];"
                 : "=r"(r0), "=r"(r1), "=r"(r2), "=r"(r3) : "r"(a));
}
DINL void mma16816(float& d0, float& d1, float& d2, float& d3,
                   uint32_t a0, uint32_t a1, uint32_t a2, uint32_t a3,
                   uint32_t b0, uint32_t b1) {
    asm volatile(
        "mma.sync.aligned.m16n8k16.row.col.f32.bf16.bf16.f32 "
        "{%0,%1,%2,%3}, {%4,%5,%6,%7}, {%8,%9}, {%0,%1,%2,%3};"
        : "+f"(d0), "+f"(d1), "+f"(d2), "+f"(d3)
        : "r"(a0), "r"(a1), "r"(a2), "r"(a3), "r"(b0), "r"(b1));
}

// ---------------- prep 1: x -> channel-last bf16 hi/lo ----------------------
__global__ void prep_x(const float* __restrict__ x) {
    __shared__ float t[144 * 33];
    int bid = blockIdx.x;                 // 8192 = 8b*32x*32y
    int b = bid >> 10, xx = (bid >> 5) & 31, y = bid & 31;
    for (int i = threadIdx.x; i < 144 * 32; i += 128) {
        int ci = i >> 5, z = i & 31;
        t[ci * 33 + z] = x[(size_t)(b * 144 + ci) * 32768 + xx * 1024 + y * 32 + z];
    }
    __syncthreads();
    size_t rb = ((((size_t)b * 32 + xx) * 32 + y) * 32) * 72;   // uint32 units
    uint32_t* oh = (uint32_t*)g_xh;
    uint32_t* ol = (uint32_t*)g_xl;
    for (int j = threadIdx.x; j < 32 * 72; j += 128) {
        int z = j / 72, cp = j % 72, ci = cp * 2;
        float f0 = t[ci * 33 + z], f1 = t[(ci + 1) * 33 + z];
        __nv_bfloat16 h0 = __float2bfloat16(f0), h1 = __float2bfloat16(f1);
        __nv_bfloat16 l0 = __float2bfloat16(f0 - __bfloat162float(h0));
        __nv_bfloat16 l1 = __float2bfloat16(f1 - __bfloat162float(h1));
        __nv_bfloat162 vh; vh.x = h0; vh.y = h1;
        __nv_bfloat162 vl; vl.x = l0; vl.y = l1;
        oh[rb + (size_t)z * 72 + cp] = *(uint32_t*)&vh;
        ol[rb + (size_t)z * 72 + cp] = *(uint32_t*)&vl;
    }
}

// ---------------- prep 2: W -> B rows hi/lo ---------------------------------
__global__ void prep_w(const float* __restrict__ W) {
    int i = blockIdx.x * 256 + threadIdx.x;
    if (i >= 2592 * 64) return;
    int row = i >> 6, cil = i & 63;
    int co = row & 31, tt = row >> 5;
    int ky = tt % 3, chunk = (tt / 3) % 3, kxkz = tt / 9;
    int kx = kxkz / 3, kz = kxkz % 3;
    int ci = chunk * 64 + cil;
    float f = (ci < 144) ? W[(size_t)(co * 144 + ci) * 27 + kx * 9 + ky * 3 + kz] : 0.f;
    __nv_bfloat16 h = __float2bfloat16(f);
    g_bh[i] = h;
    g_bl[i] = __float2bfloat16(f - __bfloat162float(h));
}

// ---------------- main: implicit GEMM via mma.sync bf16 ---------------------
// CTA: M=128 = 4oy x 32oz (oz 30,31 + oy>=30 discarded), N=32. 256 thr, 8 warps;
// warp w owns M rows [w*16, w*16+16) x all N. Grid 1920 = 8b*30ox*8oyblk.
// Unit u=(kx,chunk,kz): A slab [192 rows x 64ci] hi/lo (row = flat(y,z)+kz shift),
// B [3ky][32co][64ci] hi/lo. ky = row offset +32 in both A and B.
// smem/buf: AH 24576 | AL 24576 | BH 12288 | BL 12288 = 73728; x2 = 147456.
// 16B-granular XOR swizzle (cg ^ (row&7)) on all tiles for conflict-free ldmatrix.
static constexpr int OFF_AL = 24576;
static constexpr int OFF_BH = 49152;
static constexpr int OFF_BL = 61440;
static constexpr int BUF    = 73728;
static constexpr int SMEM_TOT = 2 * BUF;

DINL void stage_unit(int u, int b, int ox, int oy0, int tid, uint32_t bufb) {
    int kx = u / 9, chunk = (u / 3) % 3, kz = u % 3;
    int cgmax = (chunk < 2) ? 8 : 2;       // chunk 2 has only 16 valid ci
    int cgsh  = (chunk < 2) ? 3 : 1;
    int f0 = ((b * 32 + ox + kx) * 32 + oy0) * 32 + kz;
    const char* gah = (const char*)g_xh + (size_t)f0 * 288 + chunk * 128;
    const char* gal = (const char*)g_xl + (size_t)f0 * 288 + chunk * 128;
    for (int idx = tid; idx < 192 * cgmax; idx += 256) {
        int row = idx >> cgsh, cg = idx & (cgmax - 1);
        uint32_t d = bufb + row * 128 + ((cg ^ (row & 7)) << 4);
        cp16(d,          gah + (size_t)row * 288 + cg * 16);
        cp16(d + OFF_AL, gal + (size_t)row * 288 + cg * 16);
    }
    int brow0 = ((kx * 3 + kz) * 9 + chunk * 3) * 32;
    const char* gbh = (const char*)g_bh + (size_t)brow0 * 128;
    const char* gbl = (const char*)g_bl + (size_t)brow0 * 128;
    for (int idx = tid; idx < 96 * cgmax; idx += 256) {
        int row = idx >> cgsh, cg = idx & (cgmax - 1);
        uint32_t d = bufb + OFF_BH + row * 128 + ((cg ^ (row & 7)) << 4);
        cp16(d,                     gbh + (size_t)row * 128 + cg * 16);
        cp16(d + (OFF_BL - OFF_BH), gbl + (size_t)row * 128 + cg * 16);
    }
}

__global__ __launch_bounds__(256, 1)
void conv_mma(float* __restrict__ out) {
    extern __shared__ char smem[];
    uint32_t sb = smem_u32(smem);
    int tid = threadIdx.x, w = tid >> 5, lane = tid & 31;

    int bid = blockIdx.x;
    int b = bid / 240, r = bid % 240, ox = r / 8, oy0 = (r % 8) * 4;

    // Canonical ldmatrix.x4 lane geometry:
    //   lanes 0-7  -> (rows 0-7,  kblk0) -> r0
    //   lanes 8-15 -> (rows 8-15, kblk0) -> r1
    //   lanes 16-23-> (rows 0-7,  kblk1) -> r2
    //   lanes 24-31-> (rows 8-15, kblk1) -> r3
    // A fragments: {a0,a1,a2,a3} = {r0,r1,r2,r3} directly.
    // B fragments: n-tile lo = (r0,r2), n-tile hi = (r1,r3).
    int lrow = (lane & 7) + (((lane >> 3) & 1) << 3);
    int lblk = lane >> 4;
    int lsw  = lane & 7;    // == addressed row & 7 (swizzle term)

    float c[4][4];
#pragma unroll
    for (int i = 0; i < 4; i++)
#pragma unroll
        for (int j = 0; j < 4; j++) c[i][j] = 0.f;

    stage_unit(0, b, ox, oy0, tid, sb);
    cp_commit();

    for (int u = 0; u < 27; u++) {
        int chunk = (u / 3) % 3;
        uint32_t bufb = sb + (u & 1) * BUF;
        __syncthreads();
        if (u + 1 < 27) {
            stage_unit(u + 1, b, ox, oy0, tid, sb + ((u + 1) & 1) * BUF);
            cp_commit();
            cp_wait1();
        } else {
            cp_wait0();
        }
        __syncthreads();

        int ksteps = (chunk < 2) ? 4 : 1;
#pragma unroll 1
        for (int ks = 0; ks < ksteps; ks++) {
            uint32_t col = (uint32_t)(((ks * 2 + lblk) ^ lsw) << 4);
#pragma unroll
            for (int ky = 0; ky < 3; ky++) {
                uint32_t arow = (uint32_t)(ky * 32 + w * 16 + lrow) * 128;
                uint32_t ah0, ah1, ah2, ah3, al0, al1, al2, al3;
                ldm4(ah0, ah1, ah2, ah3, bufb + arow + col);
                ldm4(al0, al1, al2, al3, bufb + OFF_AL + arow + col);

                uint32_t brow0 = (uint32_t)(ky * 32 + lrow) * 128;          // n 0-15
                uint32_t brow1 = (uint32_t)(ky * 32 + 16 + lrow) * 128;     // n 16-31
                uint32_t bh0, bh1, bh2, bh3, bh4, bh5, bh6, bh7;
                ldm4(bh0, bh1, bh2, bh3, bufb + OFF_BH + brow0 + col);  // nt0=(bh0,bh2) nt1=(bh1,bh3)
                ldm4(bh4, bh5, bh6, bh7, bufb + OFF_BH + brow1 + col);  // nt2=(bh4,bh6) nt3=(bh5,bh7)
                uint32_t bl0, bl1, bl2, bl3, bl4, bl5, bl6, bl7;
                ldm4(bl0, bl1, bl2, bl3, bufb + OFF_BL + brow0 + col);
                ldm4(bl4, bl5, bl6, bl7, bufb + OFF_BL + brow1 + col);

                // pass hh
                mma16816(c[0][0], c[0][1], c[0][2], c[0][3], ah0, ah1, ah2, ah3, bh0, bh2);
                mma16816(c[1][0], c[1][1], c[1][2], c[1][3], ah0, ah1, ah2, ah3, bh1, bh3);
                mma16816(c[2][0], c[2][1], c[2][2], c[2][3], ah0, ah1, ah2, ah3, bh4, bh6);
                mma16816(c[3][0], c[3][1], c[3][2], c[3][3], ah0, ah1, ah2, ah3, bh5, bh7);
                // pass hl
                mma16816(c[0][0], c[0][1], c[0][2], c[0][3], ah0, ah1, ah2, ah3, bl0, bl2);
                mma16816(c[1][0], c[1][1], c[1][2], c[1][3], ah0, ah1, ah2, ah3, bl1, bl3);
                mma16816(c[2][0], c[2][1], c[2][2], c[2][3], ah0, ah1, ah2, ah3, bl4, bl6);
                mma16816(c[3][0], c[3][1], c[3][2], c[3][3], ah0, ah1, ah2, ah3, bl5, bl7);
                // pass lh
                mma16816(c[0][0], c[0][1], c[0][2], c[0][3], al0, al1, al2, al3, bh0, bh2);
                mma16816(c[1][0], c[1][1], c[1][2], c[1][3], al0, al1, al2, al3, bh1, bh3);
                mma16816(c[2][0], c[2][1], c[2][2], c[2][3], al0, al1, al2, al3, bh4, bh6);
                mma16816(c[3][0], c[3][1], c[3][2], c[3][3], al0, al1, al2, al3, bh5, bh7);
            }
        }
    }

    // ---- epilogue ----
    // c[nt]: d0=C[rr][n0], d1=C[rr][n0+1], d2=C[rr+8][n0], d3=C[rr+8][n0+1],
    // rr = lane>>2, n0 = nt*8 + (lane&3)*2. M row = w*16 + rr(+8).
    int rr = lane >> 2;
    int nb = (lane & 3) * 2;
#pragma unroll
    for (int half = 0; half < 2; half++) {
        int Mrow = w * 16 + rr + half * 8;
        int oy = oy0 + (Mrow >> 5);
        int oz = Mrow & 31;
        if (oy < 30 && oz < 30) {
            float* ob = out + (size_t)b * 32 * 27000 + ox * 900 + oy * 30 + oz;
#pragma unroll
            for (int nt = 0; nt < 4; nt++) {
                int n = nt * 8 + nb;
                ob[(size_t)n * 27000]       = c[nt][half * 2];
                ob[(size_t)(n + 1) * 27000] = c[nt][half * 2 + 1];
            }
        }
    }
}

// ---------------- host ------------------------------------------------------
extern "C" void kernel_launch(void* const* d_in, const int* in_sizes, int n_in,
                              void* d_out, int out_size) {
    const float* x = (const float*)d_in[0];
    const float* W = (const float*)d_in[1];
    if (n_in >= 2 && in_sizes[0] == 124416) { const float* t = x; x = W; W = t; }
    float* out = (float*)d_out;

    cudaFuncSetAttribute(conv_mma, cudaFuncAttributeMaxDynamicSharedMemorySize, SMEM_TOT);

    prep_x<<<8192, 128>>>(x);
    prep_w<<<(2592 * 64 + 255) / 256, 256>>>(W);
    conv_mma<<<1920, 256, SMEM_TOT>>>(out);
}

// round 13
// speedup vs baseline: 2.0968x; 1.1366x over previous
// R13: verbatim resubmit of R12 (M=256 + kz-merged A + 2-level pipeline);
// third broker flake streak — audit found no hang/fault path, smem 212KB legal.
#include <cuda_runtime.h>
#include <cuda_bf16.h>
#include <cstdint>

#define DINL __device__ __forceinline__

// ---------------- device scratch (no allocations allowed) -------------------
// x channel-last bf16 hi/lo: row = flat(b,x,y,z), 144 ci per row (288B).
// +1024 pad rows: window shifts read <=72 rows past the last slab start; those
// products land only in discarded oz>=30 / oy>=30 outputs. .bss zero-init.
__device__ __align__(16) __nv_bfloat16 g_xh[(262144 + 1024) * 144];
__device__ __align__(16) __nv_bfloat16 g_xl[(262144 + 1024) * 144];
// W rows: [(kx*3+kz)*9 + chunk*3 + ky][co32][ci64] = 2592 rows x 128B
__device__ __align__(16) __nv_bfloat16 g_bh[2592 * 64];
__device__ __align__(16) __nv_bfloat16 g_bl[2592 * 64];

// ---------------- PTX helpers ----------------------------------------------
DINL uint32_t smem_u32(const void* p) {
    uint32_t a;
    asm("{ .reg .u64 t; cvta.to.shared.u64 t, %1; cvt.u32.u64 %0, t; }" : "=r"(a) : "l"(p));
    return a;
}
DINL void cp16(uint32_t s, const void* g) {
    asm volatile("cp.async.cg.shared.global [%0], [%1], 16;" :: "r"(s), "l"(g));
}
DINL void cp_commit() { asm volatile("cp.async.commit_group;"); }
DINL void cp_wait2()  { asm volatile("cp.async.wait_group 2;" ::: "memory"); }
DINL void cp_wait1()  { asm volatile("cp.async.wait_group 1;" ::: "memory"); }
DINL void cp_wait0()  { asm volatile("cp.async.wait_group 0;" ::: "memory"); }

DINL void ldm4(uint32_t& r0, uint32_t& r1, uint32_t& r2, uint32_t& r3, uint32_t a) {
    asm volatile("ldmatrix.sync.aligned.m8n8.x4.shared.b16 {%0,%1,%2,%3}, [%4];"
                 : "=r"(r0), "=r"(r1), "=r"(r2), "=r"(r3) : "r"(a));
}
DINL void mma16816(float& d0, float& d1, float& d2, float& d3,
                   uint32_t a0, uint32_t a1, uint32_t a2, uint32_t a3,
                   uint32_t b0, uint32_t b1) {
    asm volatile(
        "mma.sync.aligned.m16n8k16.row.col.f32.bf16.bf16.f32 "
        "{%0,%1,%2,%3}, {%4,%5,%6,%7}, {%8,%9}, {%0,%1,%2,%3};"
        : "+f"(d0), "+f"(d1), "+f"(d2), "+f"(d3)
        : "r"(a0), "r"(a1), "r"(a2), "r"(a3), "r"(b0), "r"(b1));
}

// ---------------- prep 1: x -> channel-last bf16 hi/lo ----------------------
__global__ void prep_x(const float* __restrict__ x) {
    __shared__ float t[144 * 33];
    int bid = blockIdx.x;                 // 8192 = 8b*32x*32y
    int b = bid >> 10, xx = (bid >> 5) & 31, y = bid & 31;
    for (int i = threadIdx.x; i < 144 * 32; i += 128) {
        int ci = i >> 5, z = i & 31;
        t[ci * 33 + z] = x[(size_t)(b * 144 + ci) * 32768 + xx * 1024 + y * 32 + z];
    }
    __syncthreads();
    size_t rb = ((((size_t)b * 32 + xx) * 32 + y) * 32) * 72;   // uint32 units
    uint32_t* oh = (uint32_t*)g_xh;
    uint32_t* ol = (uint32_t*)g_xl;
    for (int j = threadIdx.x; j < 32 * 72; j += 128) {
        int z = j / 72, cp = j % 72, ci = cp * 2;
        float f0 = t[ci * 33 + z], f1 = t[(ci + 1) * 33 + z];
        __nv_bfloat16 h0 = __float2bfloat16(f0), h1 = __float2bfloat16(f1);
        __nv_bfloat16 l0 = __float2bfloat16(f0 - __bfloat162float(h0));
        __nv_bfloat16 l1 = __float2bfloat16(f1 - __bfloat162float(h1));
        __nv_bfloat162 vh; vh.x = h0; vh.y = h1;
        __nv_bfloat162 vl; vl.x = l0; vl.y = l1;
        oh[rb + (size_t)z * 72 + cp] = *(uint32_t*)&vh;
        ol[rb + (size_t)z * 72 + cp] = *(uint32_t*)&vl;
    }
}

// ---------------- prep 2: W -> B rows hi/lo ---------------------------------
__global__ void prep_w(const float* __restrict__ W) {
    int i = blockIdx.x * 256 + threadIdx.x;
    if (i >= 2592 * 64) return;
    int row = i >> 6, cil = i & 63;
    int co = row & 31, tt = row >> 5;
    int ky = tt % 3, chunk = (tt / 3) % 3, kxkz = tt / 9;
    int kx = kxkz / 3, kz = kxkz % 3;
    int ci = chunk * 64 + cil;
    float f = (ci < 144) ? W[(size_t)(co * 144 + ci) * 27 + kx * 9 + ky * 3 + kz] : 0.f;
    __nv_bfloat16 h = __float2bfloat16(f);
    g_bh[i] = h;
    g_bl[i] = __float2bfloat16(f - __bfloat162float(h));
}

// ---------------- main: implicit GEMM, M=256, kz-merged A -------------------
// CTA: M=256 = 8oy x 32oz, N=32. 256 thr, 8 warps; warp w owns M [w*32,w*32+32).
// Grid 960 = 8b * 30ox * 4oyblk.
// A unit (kx,chunk): one 328-row slab (row = flat(y_local,z)); kz & ky become
// ROW OFFSETS at read time (ky*32+kz); lane swizzle re-derived as (lane+kz)&7.
// B unit (kx,chunk,kz): 96 rows (3 ky taps x 32 co).
// smem: A 2 x (2x41984) = 167936 | B 2 x (2x12288) = 49152 -> 217088 total.
static constexpr int A_SLOT = 328 * 128;           // 41984 (hi or lo)
static constexpr int A_BUF  = 2 * A_SLOT;          // 83968
static constexpr int OFF_B  = 2 * A_BUF;           // 167936
static constexpr int B_SLOT = 96 * 128;            // 12288
static constexpr int B_BUF  = 2 * B_SLOT;          // 24576
static constexpr int SMEM_TOT = OFF_B + 2 * B_BUF; // 217088

DINL void stage_A(int u, int b, int ox, int oy0, int tid, uint32_t dst) {
    int kx = u / 3, chunk = u % 3;
    int cgmax = (chunk < 2) ? 8 : 2;
    int cgsh  = (chunk < 2) ? 3 : 1;
    int f0 = ((b * 32 + ox + kx) * 32 + oy0) * 32;
    const char* gh = (const char*)g_xh + (size_t)f0 * 288 + chunk * 128;
    const char* gl = (const char*)g_xl + (size_t)f0 * 288 + chunk * 128;
    for (int idx = tid; idx < 328 * cgmax; idx += 256) {
        int row = idx >> cgsh, cg = idx & (cgmax - 1);
        uint32_t d = dst + row * 128 + ((cg ^ (row & 7)) << 4);
        cp16(d,          gh + (size_t)row * 288 + cg * 16);
        cp16(d + A_SLOT, gl + (size_t)row * 288 + cg * 16);
    }
}
DINL void stage_B(int s, int tid, uint32_t dst) {
    int kx = s / 9, chunk = (s % 9) / 3, kz = s % 3;
    int cgmax = (chunk < 2) ? 8 : 2;
    int cgsh  = (chunk < 2) ? 3 : 1;
    int brow0 = ((kx * 3 + kz) * 9 + chunk * 3) * 32;
    const char* gh = (const char*)g_bh + (size_t)brow0 * 128;
    const char* gl = (const char*)g_bl + (size_t)brow0 * 128;
    for (int idx = tid; idx < 96 * cgmax; idx += 256) {
        int row = idx >> cgsh, cg = idx & (cgmax - 1);
        uint32_t d = dst + row * 128 + ((cg ^ (row & 7)) << 4);
        cp16(d,          gh + (size_t)row * 128 + cg * 16);
        cp16(d + B_SLOT, gl + (size_t)row * 128 + cg * 16);
    }
}

__global__ __launch_bounds__(256, 1)
void conv_mma(float* __restrict__ out) {
    extern __shared__ char smem[];
    uint32_t sb = smem_u32(smem);
    int tid = threadIdx.x, w = tid >> 5, lane = tid & 31;

    int bid = blockIdx.x;                       // 960 = 8b * 30ox * 4oyblk
    int b = bid / 120, r = bid % 120, ox = r / 4, oy0 = (r % 4) * 8;

    // canonical ldmatrix.x4 lane geometry (proven in R11)
    int lrow = (lane & 7) + (((lane >> 3) & 1) << 3);
    int lblk = lane >> 4;

    float c[2][4][4];                           // [mtile][ntile][frag]
#pragma unroll
    for (int m = 0; m < 2; m++)
#pragma unroll
        for (int n = 0; n < 4; n++)
#pragma unroll
            for (int j = 0; j < 4; j++) c[m][n][j] = 0.f;

    // prologue: A(0), B(0)
    stage_A(0, b, ox, oy0, tid, sb);
    cp_commit();
    stage_B(0, tid, sb + OFF_B);
    cp_commit();

    for (int s = 0; s < 27; s++) {
        int u = s / 3, kz = s % 3, chunk = u % 3;
        uint32_t abuf = sb + (u & 1) * A_BUF;
        uint32_t bbuf = sb + OFF_B + (s & 1) * B_BUF;

        __syncthreads();                        // readers of soon-overwritten bufs done
        int n_new = 0;
        if (kz == 0 && u + 1 < 9) {
            stage_A(u + 1, b, ox, oy0, tid, sb + ((u + 1) & 1) * A_BUF);
            cp_commit(); n_new++;
        }
        if (s + 1 < 27) {
            stage_B(s + 1, tid, sb + OFF_B + ((s + 1) & 1) * B_BUF);
            cp_commit(); n_new++;
        }
        if (n_new == 2) cp_wait2(); else if (n_new == 1) cp_wait1(); else cp_wait0();
        __syncthreads();

        int ksteps = (chunk < 2) ? 4 : 1;
        uint32_t csA = (uint32_t)((lane + kz) & 7);   // A swizzle term (row base +kz)
        uint32_t csB = (uint32_t)(lane & 7);          // B rows stay 32-aligned
#pragma unroll 1
        for (int ks = 0; ks < ksteps; ks++) {
            uint32_t colA = (uint32_t)(((ks * 2 + lblk) ^ csA) << 4);
            uint32_t colB = (uint32_t)(((ks * 2 + lblk) ^ csB) << 4);
#pragma unroll
            for (int ky = 0; ky < 3; ky++) {
                // B fragments (shared across both m-tiles)
                uint32_t br0 = (uint32_t)(ky * 32 + lrow) * 128;       // n 0-15
                uint32_t br1 = (uint32_t)(ky * 32 + 16 + lrow) * 128;  // n 16-31
                uint32_t bh0, bh1, bh2, bh3, bh4, bh5, bh6, bh7;
                ldm4(bh0, bh1, bh2, bh3, bbuf + br0 + colB);
                ldm4(bh4, bh5, bh6, bh7, bbuf + br1 + colB);
                uint32_t bl0, bl1, bl2, bl3, bl4, bl5, bl6, bl7;
                ldm4(bl0, bl1, bl2, bl3, bbuf + B_SLOT + br0 + colB);
                ldm4(bl4, bl5, bl6, bl7, bbuf + B_SLOT + br1 + colB);
#pragma unroll
                for (int m = 0; m < 2; m++) {
                    uint32_t arow =
                        (uint32_t)(w * 32 + m * 16 + ky * 32 + kz + lrow) * 128;
                    uint32_t a0, a1, a2, a3, q0, q1, q2, q3;
                    ldm4(a0, a1, a2, a3, abuf + arow + colA);            // xh
                    ldm4(q0, q1, q2, q3, abuf + A_SLOT + arow + colA);   // xl
                    // pass hh
                    mma16816(c[m][0][0], c[m][0][1], c[m][0][2], c[m][0][3], a0, a1, a2, a3, bh0, bh2);
                    mma16816(c[m][1][0], c[m][1][1], c[m][1][2], c[m][1][3], a0, a1, a2, a3, bh1, bh3);
                    mma16816(c[m][2][0], c[m][2][1], c[m][2][2], c[m][2][3], a0, a1, a2, a3, bh4, bh6);
                    mma16816(c[m][3][0], c[m][3][1], c[m][3][2], c[m][3][3], a0, a1, a2, a3, bh5, bh7);
                    // pass hl
                    mma16816(c[m][0][0], c[m][0][1], c[m][0][2], c[m][0][3], a0, a1, a2, a3, bl0, bl2);
                    mma16816(c[m][1][0], c[m][1][1], c[m][1][2], c[m][1][3], a0, a1, a2, a3, bl1, bl3);
                    mma16816(c[m][2][0], c[m][2][1], c[m][2][2], c[m][2][3], a0, a1, a2, a3, bl4, bl6);
                    mma16816(c[m][3][0], c[m][3][1], c[m][3][2], c[m][3][3], a0, a1, a2, a3, bl5, bl7);
                    // pass lh
                    mma16816(c[m][0][0], c[m][0][1], c[m][0][2], c[m][0][3], q0, q1, q2, q3, bh0, bh2);
                    mma16816(c[m][1][0], c[m][1][1], c[m][1][2], c[m][1][3], q0, q1, q2, q3, bh1, bh3);
                    mma16816(c[m][2][0], c[m][2][1], c[m][2][2], c[m][2][3], q0, q1, q2, q3, bh4, bh6);
                    mma16816(c[m][3][0], c[m][3][1], c[m][3][2], c[m][3][3], q0, q1, q2, q3, bh5, bh7);
                }
            }
        }
    }

    // ---- epilogue: Mrow = w*32 + m*16 + rr(+8); oy_local = Mrow/32, oz = Mrow%32
    int rr = lane >> 2;
    int nb = (lane & 3) * 2;
#pragma unroll
    for (int m = 0; m < 2; m++)
#pragma unroll
        for (int half = 0; half < 2; half++) {
            int Mrow = w * 32 + m * 16 + rr + half * 8;
            int oy = oy0 + (Mrow >> 5);
            int oz = Mrow & 31;
            if (oy < 30 && oz < 30) {
                float* ob = out + (size_t)b * 32 * 27000 + ox * 900 + oy * 30 + oz;
#pragma unroll
                for (int nt = 0; nt < 4; nt++) {
                    int n = nt * 8 + nb;
                    ob[(size_t)n * 27000]       = c[m][nt][half * 2];
                    ob[(size_t)(n + 1) * 27000] = c[m][nt][half * 2 + 1];
                }
            }
        }
}

// ---------------- host ------------------------------------------------------
extern "C" void kernel_launch(void* const* d_in, const int* in_sizes, int n_in,
                              void* d_out, int out_size) {
    const float* x = (const float*)d_in[0];
    const float* W = (const float*)d_in[1];
    if (n_in >= 2 && in_sizes[0] == 124416) { const float* t = x; x = W; W = t; }
    float* out = (float*)d_out;

    cudaFuncSetAttribute(conv_mma, cudaFuncAttributeMaxDynamicSharedMemorySize, SMEM_TOT);

    prep_x<<<8192, 128>>>(x);
    prep_w<<<(2592 * 64 + 255) / 256, 256>>>(W);
    conv_mma<<<960, 256, SMEM_TOT>>>(out);
}